// round 10
// baseline (speedup 1.0000x reference)
#include <cuda_runtime.h>
#include <cuda_fp16.h>
#include <cstdint>
#include <cstddef>

#define NN 8192      // nodes == in_feats
#define DF 512       // feature dim
#define NE 262144    // edges

// ---------------- device scratch (no allocations allowed) ----------------
// All mutable state is re-initialized every run (k0 zeroes flags, scan zeroes
// deg, gemm self-cleans g_cnt), so graph replays are deterministic.
__device__ int    g_deg[NN];
__device__ int    g_off[NN + 1];
__device__ int    g_cur[NN];
__device__ int    g_col[NE];
__device__ int    g_cnt[256];                 // split-tile completion counters
__device__ int    g_ready[128];               // per-k-chunk h readiness flags
__device__ int    g_ccnt[128];                // per-k-chunk node completion count
__device__ __half g_xh[(size_t)NN * DF];      // [node, feat] fp16, 8MB
__device__ __half g_hT[(size_t)NN * DF];      // [node(k), feat(n)] fp16 B operand, 8MB

// ---------------- helpers ----------------
__device__ __forceinline__ uint32_t smem_u32(const void* p) {
    uint32_t a;
    asm("{ .reg .u64 t; cvta.to.shared.u64 t, %1; cvt.u32.u64 %0, t; }"
        : "=r"(a) : "l"(p));
    return a;
}
__device__ __forceinline__ void cp_async16(uint32_t saddr, const void* gaddr) {
    asm volatile("cp.async.cg.shared.global [%0], [%1], 16;"
                 :: "r"(saddr), "l"(gaddr) : "memory");
}
#define CP_COMMIT() asm volatile("cp.async.commit_group;" ::: "memory")
#define CP_WAIT1()  asm volatile("cp.async.wait_group 1;"  ::: "memory")
#define CP_WAIT0()  asm volatile("cp.async.wait_group 0;"  ::: "memory")

#define LDSM4T(r0, r1, r2, r3, addr) \
    asm volatile("ldmatrix.sync.aligned.m8n8.x4.trans.shared.b16 {%0,%1,%2,%3}, [%4];" \
                 : "=r"(r0), "=r"(r1), "=r"(r2), "=r"(r3) : "r"(addr))

#define LDS64(v, addr) \
    asm volatile("ld.shared.v2.f32 {%0,%1}, [%2];" \
                 : "=f"((v).x), "=f"((v).y) : "r"(addr))

__device__ __forceinline__ uint32_t packh2(float lo, float hi) {
    __half2 h = __floats2half2_rn(lo, hi);
    return *reinterpret_cast<uint32_t*>(&h);
}

__device__ __forceinline__ void mma_f16(float* c,
                                        uint32_t a0, uint32_t a1, uint32_t a2, uint32_t a3,
                                        uint32_t b0, uint32_t b1) {
    asm volatile(
        "mma.sync.aligned.m16n8k16.row.col.f32.f16.f16.f32 "
        "{%0,%1,%2,%3}, {%4,%5,%6,%7}, {%8,%9}, {%0,%1,%2,%3};"
        : "+f"(c[0]), "+f"(c[1]), "+f"(c[2]), "+f"(c[3])
        : "r"(a0), "r"(a1), "r"(a2), "r"(a3), "r"(b0), "r"(b1));
}

__device__ __forceinline__ void wait_ready(int c) {
    const int* p = g_ready + c;
    while (true) {
        int f;
        asm volatile("ld.acquire.gpu.global.b32 %0, [%1];"
                     : "=r"(f) : "l"(p) : "memory");
        if (f) break;
        __nanosleep(64);
    }
}

// ---------------- fused prep head ----------------
// blocks [0,4096): transpose x [DF,NN] f32 -> g_xh [NN,DF] fp16
// blocks [4096,8192): zero out
// blocks [8192,8448): degree count (4 edges/thread); block 8192 also zeroes flags
__global__ void k0_kernel(const float* __restrict__ x, float* __restrict__ out,
                          const int* __restrict__ adj) {
    int b = blockIdx.x;
    int tid = threadIdx.x;
    if (b < 4096) {
        __shared__ float tile[32][33];
        int n0 = (b & 255) * 32;
        int d0 = (b >> 8) * 32;
        int tx = tid & 31, ty = tid >> 5;
#pragma unroll
        for (int i = 0; i < 32; i += 8)
            tile[ty + i][tx] = x[(size_t)(d0 + ty + i) * NN + n0 + tx];
        __syncthreads();
#pragma unroll
        for (int i = 0; i < 32; i += 8)
            g_xh[(size_t)(n0 + ty + i) * DF + d0 + tx] = __float2half_rn(tile[tx][ty + i]);
    } else if (b < 8192) {
        size_t i = ((size_t)(b - 4096) * 256 + tid) * 4;
        *reinterpret_cast<float4*>(out + i) = make_float4(0.f, 0.f, 0.f, 0.f);
    } else {
        if (b == 8192) {
            if (tid < 128) g_ready[tid] = 0;
            else g_ccnt[tid - 128] = 0;
        }
        int e4 = (b - 8192) * 256 + tid;
        int4 r = reinterpret_cast<const int4*>(adj)[e4];
        atomicAdd(&g_deg[r.x], 1);
        atomicAdd(&g_deg[r.y], 1);
        atomicAdd(&g_deg[r.z], 1);
        atomicAdd(&g_deg[r.w], 1);
    }
}

// exclusive scan of 8192 degrees; re-zero g_deg after reading (replay invariant)
__global__ void scan_kernel() {
    __shared__ int wsum[32];
    int t = threadIdx.x, lane = t & 31, wid = t >> 5;
    int base = t * 8;
    int l[8];
    int s = 0;
#pragma unroll
    for (int j = 0; j < 8; ++j) { s += g_deg[base + j]; l[j] = s; }
#pragma unroll
    for (int j = 0; j < 8; ++j) g_deg[base + j] = 0;
    int tot = s;
#pragma unroll
    for (int o = 1; o < 32; o <<= 1) {
        int v = __shfl_up_sync(0xffffffffu, s, o);
        if (lane >= o) s += v;
    }
    if (lane == 31) wsum[wid] = s;
    __syncthreads();
    if (wid == 0) {
        int w = wsum[lane];
#pragma unroll
        for (int o = 1; o < 32; o <<= 1) {
            int v = __shfl_up_sync(0xffffffffu, w, o);
            if (lane >= o) w += v;
        }
        wsum[lane] = w;
    }
    __syncthreads();
    int warp_base = wid ? wsum[wid - 1] : 0;
    int excl = warp_base + s - tot;
#pragma unroll
    for (int j = 0; j < 8; ++j) {
        int e = excl + ((j == 0) ? 0 : l[j - 1]);
        g_off[base + j] = e;
        g_cur[base + j] = e;
    }
    if (t == 1023) g_off[NN] = warp_base + s;
}

__global__ void scatter_kernel(const int* __restrict__ adj) {
    int e4 = blockIdx.x * 256 + threadIdx.x;
    int4 r = reinterpret_cast<const int4*>(adj)[e4];
    int4 c = reinterpret_cast<const int4*>(adj)[NE / 4 + e4];
    g_col[atomicAdd(&g_cur[r.x], 1)] = c.x;
    g_col[atomicAdd(&g_cur[r.y], 1)] = c.y;
    g_col[atomicAdd(&g_cur[r.z], 1)] = c.z;
    g_col[atomicAdd(&g_cur[r.w], 1)] = c.w;
}

// ---------------- combined kernel: persistent GEMM + co-resident agg ----------------
// bids [0,G): GEMM (1/SM, slot 1). bids [G, G+4096): agg, 2 nodes/block (slot 2).
// GEMM gates each k-chunk's B prefetch on g_ready[chunk] set by agg blocks.

#define BM 128
#define BN 128
#define BK 64
#define NKC 128
#define TOTC 32768
#define A_REGION 0
#define A_STAGE 32768          // 128 rows x 256B (64 f32)
#define B_REGION 65536
#define B_STAGE 16384
#define GEMM_SMEM 114688       // 112KB -> 2 CTAs/SM

__device__ __forceinline__ int cta_of(int c, int G) {
    return (int)(((long long)(c + 1) * G - 1) / TOTC);
}

__global__ __launch_bounds__(256, 2)
void fused_kernel(const float* __restrict__ W, float* __restrict__ out, int G) {
    extern __shared__ char smem[];
    __shared__ int s_old;
    int tid = threadIdx.x;
    int bid = blockIdx.x;

    if (bid >= G) {
        // ================= agg block: 2 nodes =================
        int np = bid - G;
        int node = np * 2 + (tid >> 7);
        int t = tid & 127;
        int beg = g_off[node];
        int end = g_off[node + 1];
        const uint2* xh = reinterpret_cast<const uint2*>(g_xh);
        float ax = 0.f, ay = 0.f, az = 0.f, aw = 0.f;
        int j = beg;
        for (; j + 4 <= end; j += 4) {
            int c0 = g_col[j], c1 = g_col[j + 1], c2 = g_col[j + 2], c3 = g_col[j + 3];
            uint2 v0 = xh[(size_t)c0 * 128 + t];
            uint2 v1 = xh[(size_t)c1 * 128 + t];
            uint2 v2 = xh[(size_t)c2 * 128 + t];
            uint2 v3 = xh[(size_t)c3 * 128 + t];
#define ACCUM(v) do {                                              \
            __half2 h0 = *reinterpret_cast<__half2*>(&(v).x);      \
            __half2 h1 = *reinterpret_cast<__half2*>(&(v).y);      \
            float2 f0 = __half22float2(h0);                        \
            float2 f1 = __half22float2(h1);                        \
            ax += f0.x; ay += f0.y; az += f1.x; aw += f1.y; } while (0)
            ACCUM(v0); ACCUM(v1); ACCUM(v2); ACCUM(v3);
        }
        for (; j < end; ++j) {
            uint2 v = xh[(size_t)g_col[j] * 128 + t];
            ACCUM(v);
        }
#undef ACCUM
        float inv = 1.0f / fmaxf((float)(end - beg), 1.0f);
        __half2 o0 = __floats2half2_rn(ax * inv, ay * inv);
        __half2 o1 = __floats2half2_rn(az * inv, aw * inv);
        uint2 v;
        v.x = *reinterpret_cast<uint32_t*>(&o0);
        v.y = *reinterpret_cast<uint32_t*>(&o1);
        *reinterpret_cast<uint2*>(g_hT + (size_t)node * DF + t * 4) = v;

        __threadfence();
        __syncthreads();
        if (tid == 0) {
            int c = (np * 2) >> 6;     // both nodes in same 64-node chunk
            int done = atomicAdd(&g_ccnt[c], 2);
            if (done == 62) {
                __threadfence();
                const int* p = g_ready + c;
                asm volatile("st.release.gpu.global.b32 [%0], %1;"
                             :: "l"(p), "r"(1) : "memory");
            }
        }
        return;
    }

    // ================= GEMM block =================
    uint32_t sb = smem_u32(smem);
    int wid  = tid >> 5;
    int lane = tid & 31;

    int warp_m = (wid & 1) * 64;
    int warp_n = (wid >> 1) * 32;
    int lq = lane & 3, lh = lane >> 2;

    // A f32 fragment addressing: row*256 + ((k*4) ^ (lh<<5))
    uint32_t Xl = (uint32_t)(lh << 5);
    uint32_t a_rb[4];
#pragma unroll
    for (int mt = 0; mt < 4; ++mt)
        a_rb[mt] = (uint32_t)((warp_m + mt * 16 + lh) * 256);

    // B ldmatrix.trans addressing (tile: 64 k-rows x 256B of n fp16)
    int g_grp = lane >> 3;
    int kr_local = (g_grp & 1) * 8 + (lane & 7);
    uint32_t b_off[2];
#pragma unroll
    for (int p = 0; p < 2; ++p) {
        int nc = warp_n + (2 * p + (g_grp >> 1)) * 8;
        b_off[p] = (uint32_t)(kr_local * 256 + ((nc * 2) ^ ((lane & 7) << 4)));
    }

    // cp.async coords
    int a_r = tid >> 4;           // A: row (+16*i), u16 = tid&15
    int a_u = tid & 15;
    int b_k = tid >> 4;           // B: k-row (+16*i), 16B n-chunk = tid&15
    int b_nc = tid & 15;

    const __half* B = g_hT;
    int max_seen = -1;

    int cta = bid;
    int s = (int)(((long long)TOTC * cta) / G);
    int e = (int)(((long long)TOTC * (cta + 1)) / G);

    while (s < e) {
        int tile = s >> 7;
        int k0 = s - (tile << 7);
        int kend = e - (tile << 7);
        if (kend > NKC) kend = NKC;
        int nk = kend - k0;
        int m0 = (tile & 63) * BM;
        int n0 = (tile >> 6) * BN;
        bool full = (k0 == 0 && kend == NKC);

        float acc[4][4][4];
#pragma unroll
        for (int mt = 0; mt < 4; ++mt)
#pragma unroll
            for (int nt = 0; nt < 4; ++nt)
#pragma unroll
                for (int i = 0; i < 4; ++i) acc[mt][nt][i] = 0.f;

        auto cpA = [&](int kt, int stage) {
            uint32_t ab = sb + A_REGION + stage * A_STAGE;
#pragma unroll
            for (int i = 0; i < 8; ++i) {
                int row = a_r + i * 16;
                uint32_t so = (uint32_t)(row * 256 + ((a_u * 16) ^ ((row & 7) << 5)));
                cp_async16(ab + so, W + (size_t)(m0 + row) * NN + kt * BK + a_u * 4);
            }
            CP_COMMIT();
        };
        auto cpB = [&](int kt, int stage) {
            uint32_t bbuf = sb + B_REGION + stage * B_STAGE;
#pragma unroll
            for (int i = 0; i < 4; ++i) {
                int k = b_k + i * 16;
                uint32_t so = (uint32_t)(k * 256 + ((b_nc * 16) ^ ((k & 7) << 4)));
                cp_async16(bbuf + so, B + (size_t)(kt * BK + k) * DF + n0 + b_nc * 8);
            }
            CP_COMMIT();
        };
        auto gate = [&](int kp) {
            if (kp > max_seen) {
                if (tid == 0) wait_ready(kp);
                max_seen = kp;
            }
        };

        // prologue: A(k0) first (ungated, overlaps flag wait), then gated B
        cpA(k0, k0 & 1);                       // group [A0]
        gate(k0);
        if (nk > 1) gate(k0 + 1);
        __syncthreads();
        cpB(k0, k0 % 3);                       // group [B0]
        if (nk > 1) cpB(k0 + 1, (k0 + 1) % 3); // group [B1]

        for (int i = 0; i < nk; ++i) {
            int kt = k0 + i;
            if (i + 2 < nk) gate(kt + 2);
            if (i == nk - 1) { CP_WAIT0(); } else { CP_WAIT1(); }
            __syncthreads();

            if (i + 1 < nk) cpA(kt + 1, (kt + 1) & 1);      // group [A(i+1)]
            if (i + 2 < nk) cpB(kt + 2, (kt + 2) % 3);      // group [B(i+2)]

            uint32_t abuf = sb + A_REGION + (kt & 1) * A_STAGE;
            uint32_t bbuf = sb + B_REGION + (kt % 3) * B_STAGE;

#pragma unroll
            for (int c = 0; c < 4; ++c) {
                uint32_t ka = ((uint32_t)(c * 64 + lq * 8)) ^ Xl;
                uint32_t kb = ((uint32_t)(c * 64 + lq * 8 + 32)) ^ Xl;
                uint32_t af[4][4];
#pragma unroll
                for (int mt = 0; mt < 4; ++mt) {
                    uint32_t base = abuf + a_rb[mt];
                    float2 p0, p1, p2, p3;
                    LDS64(p0, base + ka);
                    LDS64(p1, base + 2048 + ka);
                    LDS64(p2, base + kb);
                    LDS64(p3, base + 2048 + kb);
                    af[mt][0] = packh2(p0.x, p0.y);
                    af[mt][1] = packh2(p1.x, p1.y);
                    af[mt][2] = packh2(p2.x, p2.y);
                    af[mt][3] = packh2(p3.x, p3.y);
                }
                uint32_t bf[4][2];
#pragma unroll
                for (int p = 0; p < 2; ++p) {
                    uint32_t ptr = bbuf + (uint32_t)(c * 4096) + b_off[p];
                    uint32_t r0, r1, r2, r3;
                    LDSM4T(r0, r1, r2, r3, ptr);
                    bf[2 * p][0] = r0;     bf[2 * p][1] = r1;
                    bf[2 * p + 1][0] = r2; bf[2 * p + 1][1] = r3;
                }
#pragma unroll
                for (int mt = 0; mt < 4; ++mt)
#pragma unroll
                    for (int nt = 0; nt < 4; ++nt)
                        mma_f16(acc[mt][nt],
                                af[mt][0], af[mt][1], af[mt][2], af[mt][3],
                                bf[nt][0], bf[nt][1]);
            }
        }

        // ---- epilogue ----
#pragma unroll
        for (int mt = 0; mt < 4; ++mt) {
            int m_lo = m0 + warp_m + mt * 16 + lh;
            int m_hi = m_lo + 8;
#pragma unroll
            for (int nt = 0; nt < 4; ++nt) {
                int nb = n0 + warp_n + nt * 8 + 2 * lq;
                float* o0 = out + (size_t)nb * NN;
                float* o1 = o0 + NN;
                if (full) {
                    o0[m_lo] = fmaxf(acc[mt][nt][0], 0.f);
                    o1[m_lo] = fmaxf(acc[mt][nt][1], 0.f);
                    o0[m_hi] = fmaxf(acc[mt][nt][2], 0.f);
                    o1[m_hi] = fmaxf(acc[mt][nt][3], 0.f);
                } else {
                    atomicAdd(o0 + m_lo, acc[mt][nt][0]);
                    atomicAdd(o1 + m_lo, acc[mt][nt][1]);
                    atomicAdd(o0 + m_hi, acc[mt][nt][2]);
                    atomicAdd(o1 + m_hi, acc[mt][nt][3]);
                }
            }
        }

        if (!full) {
            int writers = cta_of(tile * NKC + NKC - 1, G) - cta_of(tile * NKC, G) + 1;
            __threadfence();
            __syncthreads();
            if (tid == 0) s_old = atomicAdd(&g_cnt[tile], 1);
            __syncthreads();
            if (s_old == writers - 1) {
                __threadfence();
#pragma unroll
                for (int i = 0; i < 16; ++i) {
                    int idx = tid + i * 256;
                    int row = idx >> 5, c4 = idx & 31;
                    float4* pp = reinterpret_cast<float4*>(
                        out + (size_t)(n0 + row) * NN + m0) + c4;
                    float4 v = *pp;
                    v.x = fmaxf(v.x, 0.f); v.y = fmaxf(v.y, 0.f);
                    v.z = fmaxf(v.z, 0.f); v.w = fmaxf(v.w, 0.f);
                    *pp = v;
                }
                if (tid == 0) g_cnt[tile] = 0;   // replay invariant
            }
        }
        __syncthreads();

        s = (tile << 7) + kend;
    }
}

// ---------------- launcher ----------------
extern "C" void kernel_launch(void* const* d_in, const int* in_sizes, int n_in,
                              void* d_out, int out_size) {
    (void)in_sizes; (void)n_in; (void)out_size;
    const float* x   = (const float*)d_in[0];   // [512, 8192] f32
    const int*   adj = (const int*)d_in[1];     // [2, 262144] i32
    const float* W   = (const float*)d_in[2];   // [8192, 8192] f32
    float* out = (float*)d_out;                 // [512, 8192] f32

    int dev = 0, G = 148;
    cudaGetDevice(&dev);
    cudaDeviceGetAttribute(&G, cudaDevAttrMultiProcessorCount, dev);

    k0_kernel<<<8448, 256>>>(x, out, adj);
    scan_kernel<<<1, 1024>>>();
    scatter_kernel<<<NE / 1024, 256>>>(adj);

    cudaFuncSetAttribute(fused_kernel, cudaFuncAttributeMaxDynamicSharedMemorySize, GEMM_SMEM);
    fused_kernel<<<G + 4096, 256, GEMM_SMEM>>>(W, out, G);
}

// round 11
// speedup vs baseline: 1.3819x; 1.3819x over previous
#include <cuda_runtime.h>
#include <cuda_fp16.h>
#include <cstdint>
#include <cstddef>

#define NN 8192      // nodes == in_feats
#define DF 512       // feature dim
#define NE 262144    // edges

// ---------------- device scratch (no allocations allowed) ----------------
// g_deg / g_cnt are zero at module load; every run re-zeroes them after use,
// so each graph replay deterministically sees zeroed state.
__device__ int    g_deg[NN];
__device__ int    g_off[NN + 1];
__device__ int    g_cur[NN];
__device__ int    g_col[NE];
__device__ int    g_cnt[256];                 // split-tile completion counters
__device__ __half g_xh[(size_t)NN * DF];      // [node, feat] fp16, 8MB
__device__ __half g_hT[(size_t)NN * DF];      // [node(k), feat(n)] fp16 B operand, 8MB

// ---------------- helpers ----------------
__device__ __forceinline__ uint32_t smem_u32(const void* p) {
    uint32_t a;
    asm("{ .reg .u64 t; cvta.to.shared.u64 t, %1; cvt.u32.u64 %0, t; }"
        : "=r"(a) : "l"(p));
    return a;
}
__device__ __forceinline__ void cp_async16(uint32_t saddr, const void* gaddr) {
    asm volatile("cp.async.cg.shared.global [%0], [%1], 16;"
                 :: "r"(saddr), "l"(gaddr) : "memory");
}
#define CP_COMMIT() asm volatile("cp.async.commit_group;" ::: "memory")
#define CP_WAIT1()  asm volatile("cp.async.wait_group 1;"  ::: "memory")
#define CP_WAIT0()  asm volatile("cp.async.wait_group 0;"  ::: "memory")

#define LDSM4(r0, r1, r2, r3, addr) \
    asm volatile("ldmatrix.sync.aligned.m8n8.x4.shared.b16 {%0,%1,%2,%3}, [%4];" \
                 : "=r"(r0), "=r"(r1), "=r"(r2), "=r"(r3) : "r"(addr))
#define LDSM4T(r0, r1, r2, r3, addr) \
    asm volatile("ldmatrix.sync.aligned.m8n8.x4.trans.shared.b16 {%0,%1,%2,%3}, [%4];" \
                 : "=r"(r0), "=r"(r1), "=r"(r2), "=r"(r3) : "r"(addr))

__device__ __forceinline__ void mma_f16(float* c,
                                        uint32_t a0, uint32_t a1, uint32_t a2, uint32_t a3,
                                        uint32_t b0, uint32_t b1) {
    asm volatile(
        "mma.sync.aligned.m16n8k16.row.col.f32.f16.f16.f32 "
        "{%0,%1,%2,%3}, {%4,%5,%6,%7}, {%8,%9}, {%0,%1,%2,%3};"
        : "+f"(c[0]), "+f"(c[1]), "+f"(c[2]), "+f"(c[3])
        : "r"(a0), "r"(a1), "r"(a2), "r"(a3), "r"(b0), "r"(b1));
}

// ---------------- fused prep head ----------------
// blocks [0,4096): transpose x [DF,NN] f32 -> g_xh [NN,DF] fp16
// blocks [4096,8192): zero out
// blocks [8192,8448): degree count, 4 edges/thread (g_deg pre-zeroed invariant)
__global__ void k0_kernel(const float* __restrict__ x, float* __restrict__ out,
                          const int* __restrict__ adj) {
    int b = blockIdx.x;
    int tid = threadIdx.x;
    if (b < 4096) {
        __shared__ float tile[32][33];
        int n0 = (b & 255) * 32;
        int d0 = (b >> 8) * 32;
        int tx = tid & 31, ty = tid >> 5;
#pragma unroll
        for (int i = 0; i < 32; i += 8)
            tile[ty + i][tx] = x[(size_t)(d0 + ty + i) * NN + n0 + tx];
        __syncthreads();
#pragma unroll
        for (int i = 0; i < 32; i += 8)
            g_xh[(size_t)(n0 + ty + i) * DF + d0 + tx] = __float2half_rn(tile[tx][ty + i]);
    } else if (b < 8192) {
        size_t i = ((size_t)(b - 4096) * 256 + tid) * 4;
        *reinterpret_cast<float4*>(out + i) = make_float4(0.f, 0.f, 0.f, 0.f);
    } else {
        int e4 = (b - 8192) * 256 + tid;              // 0..65535, 4 edges each
        int4 r = reinterpret_cast<const int4*>(adj)[e4];
        atomicAdd(&g_deg[r.x], 1);
        atomicAdd(&g_deg[r.y], 1);
        atomicAdd(&g_deg[r.z], 1);
        atomicAdd(&g_deg[r.w], 1);
    }
}

// exclusive scan of 8192 degrees; re-zero g_deg after reading (replay invariant)
__global__ void scan_kernel() {
    __shared__ int wsum[32];
    int t = threadIdx.x, lane = t & 31, wid = t >> 5;
    int base = t * 8;
    int l[8];
    int s = 0;
#pragma unroll
    for (int j = 0; j < 8; ++j) { s += g_deg[base + j]; l[j] = s; }
#pragma unroll
    for (int j = 0; j < 8; ++j) g_deg[base + j] = 0;
    int tot = s;
#pragma unroll
    for (int o = 1; o < 32; o <<= 1) {
        int v = __shfl_up_sync(0xffffffffu, s, o);
        if (lane >= o) s += v;
    }
    if (lane == 31) wsum[wid] = s;
    __syncthreads();
    if (wid == 0) {
        int w = wsum[lane];
#pragma unroll
        for (int o = 1; o < 32; o <<= 1) {
            int v = __shfl_up_sync(0xffffffffu, w, o);
            if (lane >= o) w += v;
        }
        wsum[lane] = w;
    }
    __syncthreads();
    int warp_base = wid ? wsum[wid - 1] : 0;
    int excl = warp_base + s - tot;
#pragma unroll
    for (int j = 0; j < 8; ++j) {
        int e = excl + ((j == 0) ? 0 : l[j - 1]);
        g_off[base + j] = e;
        g_cur[base + j] = e;
    }
    if (t == 1023) g_off[NN] = warp_base + s;
}

// 4 edges/thread, int4 loads of both adj rows
__global__ void scatter_kernel(const int* __restrict__ adj) {
    int e4 = blockIdx.x * 256 + threadIdx.x;   // 0..65535
    int4 r = reinterpret_cast<const int4*>(adj)[e4];
    int4 c = reinterpret_cast<const int4*>(adj)[NE / 4 + e4];
    g_col[atomicAdd(&g_cur[r.x], 1)] = c.x;
    g_col[atomicAdd(&g_cur[r.y], 1)] = c.y;
    g_col[atomicAdd(&g_cur[r.z], 1)] = c.z;
    g_col[atomicAdd(&g_cur[r.w], 1)] = c.w;
}

// 2 nodes per 128-thread block; 64 threads per node, 8 feats (1 uint4) each.
// 8-edge unroll -> 8 outstanding LDG.128 gathers per thread. f32 accumulate,
// write h^T contiguously: g_hT[node*DF + t*8].
__global__ void agg_kernel() {
    int node = blockIdx.x * 2 + (threadIdx.x >> 6);
    int t = threadIdx.x & 63;                       // uint4 index in node row
    int beg = g_off[node];
    int end = g_off[node + 1];
    const uint4* xh4 = reinterpret_cast<const uint4*>(g_xh);  // 64 uint4 per row
    float a0 = 0.f, a1 = 0.f, a2 = 0.f, a3 = 0.f;
    float a4 = 0.f, a5 = 0.f, a6 = 0.f, a7 = 0.f;

#define ACCUM(v) do {                                               \
        const __half2* hp = reinterpret_cast<const __half2*>(&(v)); \
        float2 f0 = __half22float2(hp[0]);                          \
        float2 f1 = __half22float2(hp[1]);                          \
        float2 f2 = __half22float2(hp[2]);                          \
        float2 f3 = __half22float2(hp[3]);                          \
        a0 += f0.x; a1 += f0.y; a2 += f1.x; a3 += f1.y;             \
        a4 += f2.x; a5 += f2.y; a6 += f3.x; a7 += f3.y; } while (0)

    int j = beg;
    for (; j + 8 <= end; j += 8) {
        int c0 = g_col[j],     c1 = g_col[j + 1], c2 = g_col[j + 2], c3 = g_col[j + 3];
        int c4 = g_col[j + 4], c5 = g_col[j + 5], c6 = g_col[j + 6], c7 = g_col[j + 7];
        uint4 v0 = xh4[(size_t)c0 * 64 + t];
        uint4 v1 = xh4[(size_t)c1 * 64 + t];
        uint4 v2 = xh4[(size_t)c2 * 64 + t];
        uint4 v3 = xh4[(size_t)c3 * 64 + t];
        uint4 v4 = xh4[(size_t)c4 * 64 + t];
        uint4 v5 = xh4[(size_t)c5 * 64 + t];
        uint4 v6 = xh4[(size_t)c6 * 64 + t];
        uint4 v7 = xh4[(size_t)c7 * 64 + t];
        ACCUM(v0); ACCUM(v1); ACCUM(v2); ACCUM(v3);
        ACCUM(v4); ACCUM(v5); ACCUM(v6); ACCUM(v7);
    }
    for (; j < end; ++j) {
        uint4 v = xh4[(size_t)g_col[j] * 64 + t];
        ACCUM(v);
    }
#undef ACCUM

    float inv = 1.0f / fmaxf((float)(end - beg), 1.0f);
    __half2 h0 = __floats2half2_rn(a0 * inv, a1 * inv);
    __half2 h1 = __floats2half2_rn(a2 * inv, a3 * inv);
    __half2 h2 = __floats2half2_rn(a4 * inv, a5 * inv);
    __half2 h3 = __floats2half2_rn(a6 * inv, a7 * inv);
    uint4 v;
    v.x = *reinterpret_cast<uint32_t*>(&h0);
    v.y = *reinterpret_cast<uint32_t*>(&h1);
    v.z = *reinterpret_cast<uint32_t*>(&h2);
    v.w = *reinterpret_cast<uint32_t*>(&h3);
    *reinterpret_cast<uint4*>(g_hT + (size_t)node * DF + t * 8) = v;
}

// ---------------- balanced persistent fp16 GEMM, fused relu ----------------
#define BM 128
#define BN 128
#define BK 64
#define NKC 128
#define TOTC 32768
#define TILE_BYTES 16384
#define A_REGION 0
#define B_REGION 32768
#define GEMM_SMEM 81920

__device__ __forceinline__ int cta_of(int c, int G) {
    return (int)(((long long)(c + 1) * G - 1) / TOTC);
}

__global__ __launch_bounds__(256, 1)
void gemm_kernel(const float* __restrict__ W, float* __restrict__ out, int G) {
    extern __shared__ char smem[];
    __shared__ int s_old;
    uint32_t sb = smem_u32(smem);
    int tid  = threadIdx.x;
    int wid  = tid >> 5;
    int lane = tid & 31;

    int warp_m = (wid & 1) * 64;
    int warp_n = (wid >> 1) * 32;
    int lq = lane & 3, lh = lane >> 2;

    int a_r_lane = (lane & 7) + 8 * ((lane >> 3) & 1);
    uint32_t a_kx = (uint32_t)(16 * (lane >> 4));
    uint32_t a_row128[4], a_xr[4];
#pragma unroll
    for (int mt = 0; mt < 4; ++mt) {
        int r = warp_m + mt * 16 + a_r_lane;
        a_row128[mt] = (uint32_t)(r * 128);
        a_xr[mt] = (uint32_t)((r & 7) << 4);
    }
    int g_grp = lane >> 3;
    int kr_local = (g_grp & 1) * 8 + (lane & 7);
    uint32_t b_off[2];
#pragma unroll
    for (int p = 0; p < 2; ++p) {
        int nc = warp_n + (2 * p + (g_grp >> 1)) * 8;
        b_off[p] = (uint32_t)(kr_local * 256 + ((nc * 2) ^ ((lane & 7) << 4)));
    }

    int a_r0 = tid >> 4;
    int a_c4 = tid & 15;
    int b_k  = tid >> 4;
    int b_nc = tid & 15;

    const __half* B = g_hT;
    float4 areg[8];

    int cta = blockIdx.x;
    int s = (int)(((long long)TOTC * cta) / G);
    int e = (int)(((long long)TOTC * (cta + 1)) / G);

    while (s < e) {
        int tile = s >> 7;
        int k0 = s - (tile << 7);
        int kend = e - (tile << 7);
        if (kend > NKC) kend = NKC;
        int nk = kend - k0;
        int m0 = (tile & 63) * BM;
        int n0 = (tile >> 6) * BN;
        bool full = (k0 == 0 && kend == NKC);

        float acc[4][4][4];
#pragma unroll
        for (int mt = 0; mt < 4; ++mt)
#pragma unroll
            for (int nt = 0; nt < 4; ++nt)
#pragma unroll
                for (int i = 0; i < 4; ++i) acc[mt][nt][i] = 0.f;

        auto ldA = [&](int kt) {
#pragma unroll
            for (int i = 0; i < 8; ++i) {
                int row = a_r0 + i * 16;
                areg[i] = *reinterpret_cast<const float4*>(
                    W + (size_t)(m0 + row) * NN + kt * BK + a_c4 * 4);
            }
        };
        auto stsA = [&](int stage) {
            char* ab = smem + A_REGION + stage * TILE_BYTES;
            int colb = a_c4 * 8;
#pragma unroll
            for (int i = 0; i < 8; ++i) {
                int row = a_r0 + i * 16;
                uint32_t off = (uint32_t)(row * 128 + (colb ^ ((row & 7) << 4)));
                __half2 h0 = __floats2half2_rn(areg[i].x, areg[i].y);
                __half2 h1 = __floats2half2_rn(areg[i].z, areg[i].w);
                uint2 v;
                v.x = *reinterpret_cast<uint32_t*>(&h0);
                v.y = *reinterpret_cast<uint32_t*>(&h1);
                *reinterpret_cast<uint2*>(ab + off) = v;
            }
        };
        auto cpB = [&](int kt, int stage) {
            uint32_t bbuf = sb + B_REGION + stage * TILE_BYTES;
#pragma unroll
            for (int i = 0; i < 4; ++i) {
                int k = b_k + i * 16;
                uint32_t so = (uint32_t)(k * 256 + ((b_nc * 16) ^ ((k & 7) << 4)));
                cp_async16(bbuf + so, B + (size_t)(kt * BK + k) * DF + n0 + b_nc * 8);
            }
            CP_COMMIT();
        };

        ldA(k0);
        cpB(k0, 0);
        if (nk > 1) cpB(k0 + 1, 1);
        stsA(0);
        if (nk > 1) ldA(k0 + 1);

        for (int i = 0; i < nk; ++i) {
            if (i == nk - 1) { CP_WAIT0(); } else { CP_WAIT1(); }
            __syncthreads();

            if (i + 1 < nk) stsA((i + 1) & 1);
            if (i + 2 < nk) {
                ldA(k0 + i + 2);
                cpB(k0 + i + 2, (i + 2) % 3);
            }

            uint32_t abuf = sb + A_REGION + (i & 1) * TILE_BYTES;
            uint32_t bbuf = sb + B_REGION + (i % 3) * TILE_BYTES;

#pragma unroll
            for (int c = 0; c < 4; ++c) {
                uint32_t cb = (uint32_t)(c * 32);
                uint32_t af[4][4];
#pragma unroll
                for (int mt = 0; mt < 4; ++mt) {
                    uint32_t ptr = abuf + a_row128[mt] + ((cb + a_kx) ^ a_xr[mt]);
                    LDSM4(af[mt][0], af[mt][1], af[mt][2], af[mt][3], ptr);
                }
                uint32_t bf[4][2];
#pragma unroll
                for (int p = 0; p < 2; ++p) {
                    uint32_t ptr = bbuf + (uint32_t)(c * 4096) + b_off[p];
                    uint32_t r0, r1, r2, r3;
                    LDSM4T(r0, r1, r2, r3, ptr);
                    bf[2 * p][0] = r0;     bf[2 * p][1] = r1;
                    bf[2 * p + 1][0] = r2; bf[2 * p + 1][1] = r3;
                }
#pragma unroll
                for (int mt = 0; mt < 4; ++mt)
#pragma unroll
                    for (int nt = 0; nt < 4; ++nt)
                        mma_f16(acc[mt][nt],
                                af[mt][0], af[mt][1], af[mt][2], af[mt][3],
                                bf[nt][0], bf[nt][1]);
            }
        }

#pragma unroll
        for (int mt = 0; mt < 4; ++mt) {
            int m_lo = m0 + warp_m + mt * 16 + lh;
            int m_hi = m_lo + 8;
#pragma unroll
            for (int nt = 0; nt < 4; ++nt) {
                int nb = n0 + warp_n + nt * 8 + 2 * lq;
                float* o0 = out + (size_t)nb * NN;
                float* o1 = o0 + NN;
                if (full) {
                    o0[m_lo] = fmaxf(acc[mt][nt][0], 0.f);
                    o1[m_lo] = fmaxf(acc[mt][nt][1], 0.f);
                    o0[m_hi] = fmaxf(acc[mt][nt][2], 0.f);
                    o1[m_hi] = fmaxf(acc[mt][nt][3], 0.f);
                } else {
                    atomicAdd(o0 + m_lo, acc[mt][nt][0]);
                    atomicAdd(o1 + m_lo, acc[mt][nt][1]);
                    atomicAdd(o0 + m_hi, acc[mt][nt][2]);
                    atomicAdd(o1 + m_hi, acc[mt][nt][3]);
                }
            }
        }

        if (!full) {
            int writers = cta_of(tile * NKC + NKC - 1, G) - cta_of(tile * NKC, G) + 1;
            __threadfence();
            __syncthreads();
            if (tid == 0) s_old = atomicAdd(&g_cnt[tile], 1);
            __syncthreads();
            if (s_old == writers - 1) {
                __threadfence();
#pragma unroll
                for (int i = 0; i < 16; ++i) {
                    int idx = tid + i * 256;
                    int row = idx >> 5, c4 = idx & 31;
                    float4* pp = reinterpret_cast<float4*>(
                        out + (size_t)(n0 + row) * NN + m0) + c4;
                    float4 v = *pp;
                    v.x = fmaxf(v.x, 0.f); v.y = fmaxf(v.y, 0.f);
                    v.z = fmaxf(v.z, 0.f); v.w = fmaxf(v.w, 0.f);
                    *pp = v;
                }
                if (tid == 0) g_cnt[tile] = 0;   // replay invariant
            }
        }
        __syncthreads();

        s = (tile << 7) + kend;
    }
}

// ---------------- launcher ----------------
extern "C" void kernel_launch(void* const* d_in, const int* in_sizes, int n_in,
                              void* d_out, int out_size) {
    (void)in_sizes; (void)n_in; (void)out_size;
    const float* x   = (const float*)d_in[0];   // [512, 8192] f32
    const int*   adj = (const int*)d_in[1];     // [2, 262144] i32
    const float* W   = (const float*)d_in[2];   // [8192, 8192] f32
    float* out = (float*)d_out;                 // [512, 8192] f32

    int dev = 0, G = 148;
    cudaGetDevice(&dev);
    cudaDeviceGetAttribute(&G, cudaDevAttrMultiProcessorCount, dev);

    k0_kernel<<<8448, 256>>>(x, out, adj);
    scan_kernel<<<1, 1024>>>();
    scatter_kernel<<<NE / 1024, 256>>>(adj);
    agg_kernel<<<NN / 2, 128>>>();

    cudaFuncSetAttribute(gemm_kernel, cudaFuncAttributeMaxDynamicSharedMemorySize, GEMM_SMEM);
    gemm_kernel<<<G, 256, GEMM_SMEM>>>(W, out, G);
}

// round 12
// speedup vs baseline: 2.0775x; 1.5034x over previous
#include <cuda_runtime.h>
#include <cuda_fp16.h>
#include <cstdint>
#include <cstddef>

#define NN 8192      // nodes == in_feats
#define DF 512       // feature dim
#define NE 262144    // edges

// ---------------- device scratch (no allocations allowed) ----------------
// g_deg / g_cnt are zero at module load; every run re-zeroes them after use,
// so each graph replay deterministically sees zeroed state.
__device__ int    g_deg[NN];
__device__ int    g_off[NN + 1];
__device__ int    g_cur[NN];
__device__ int    g_col[NE];
__device__ int    g_cnt[256];                 // split-tile completion counters
__device__ __half g_xh[(size_t)NN * DF];      // [node, feat] fp16, 8MB
__device__ __half g_hT[(size_t)NN * DF];      // [node(k), feat(n)] fp16 B operand, 8MB

// ---------------- helpers ----------------
__device__ __forceinline__ uint32_t smem_u32(const void* p) {
    uint32_t a;
    asm("{ .reg .u64 t; cvta.to.shared.u64 t, %1; cvt.u32.u64 %0, t; }"
        : "=r"(a) : "l"(p));
    return a;
}
__device__ __forceinline__ void cp_async16(uint32_t saddr, const void* gaddr) {
    asm volatile("cp.async.cg.shared.global [%0], [%1], 16;"
                 :: "r"(saddr), "l"(gaddr) : "memory");
}
#define CP_COMMIT() asm volatile("cp.async.commit_group;" ::: "memory")
#define CP_WAIT1()  asm volatile("cp.async.wait_group 1;"  ::: "memory")
#define CP_WAIT0()  asm volatile("cp.async.wait_group 0;"  ::: "memory")

#define LDSM4(r0, r1, r2, r3, addr) \
    asm volatile("ldmatrix.sync.aligned.m8n8.x4.shared.b16 {%0,%1,%2,%3}, [%4];" \
                 : "=r"(r0), "=r"(r1), "=r"(r2), "=r"(r3) : "r"(addr))
#define LDSM4T(r0, r1, r2, r3, addr) \
    asm volatile("ldmatrix.sync.aligned.m8n8.x4.trans.shared.b16 {%0,%1,%2,%3}, [%4];" \
                 : "=r"(r0), "=r"(r1), "=r"(r2), "=r"(r3) : "r"(addr))

__device__ __forceinline__ void mma_f16(float* c,
                                        uint32_t a0, uint32_t a1, uint32_t a2, uint32_t a3,
                                        uint32_t b0, uint32_t b1) {
    asm volatile(
        "mma.sync.aligned.m16n8k16.row.col.f32.f16.f16.f32 "
        "{%0,%1,%2,%3}, {%4,%5,%6,%7}, {%8,%9}, {%0,%1,%2,%3};"
        : "+f"(c[0]), "+f"(c[1]), "+f"(c[2]), "+f"(c[3])
        : "r"(a0), "r"(a1), "r"(a2), "r"(a3), "r"(b0), "r"(b1));
}

// ---------------- fused prep head ----------------
// blocks [0,4096): transpose x [DF,NN] f32 -> g_xh [NN,DF] fp16
// blocks [4096,8192): zero out
// blocks [8192,8448): degree count, 4 edges/thread (g_deg pre-zeroed invariant)
__global__ void k0_kernel(const float* __restrict__ x, float* __restrict__ out,
                          const int* __restrict__ adj) {
    int b = blockIdx.x;
    int tid = threadIdx.x;
    if (b < 4096) {
        __shared__ float tile[32][33];
        int n0 = (b & 255) * 32;
        int d0 = (b >> 8) * 32;
        int tx = tid & 31, ty = tid >> 5;
#pragma unroll
        for (int i = 0; i < 32; i += 8)
            tile[ty + i][tx] = x[(size_t)(d0 + ty + i) * NN + n0 + tx];
        __syncthreads();
#pragma unroll
        for (int i = 0; i < 32; i += 8)
            g_xh[(size_t)(n0 + ty + i) * DF + d0 + tx] = __float2half_rn(tile[tx][ty + i]);
    } else if (b < 8192) {
        size_t i = ((size_t)(b - 4096) * 256 + tid) * 4;
        *reinterpret_cast<float4*>(out + i) = make_float4(0.f, 0.f, 0.f, 0.f);
    } else {
        int e4 = (b - 8192) * 256 + tid;              // 0..65535, 4 edges each
        int4 r = reinterpret_cast<const int4*>(adj)[e4];
        atomicAdd(&g_deg[r.x], 1);
        atomicAdd(&g_deg[r.y], 1);
        atomicAdd(&g_deg[r.z], 1);
        atomicAdd(&g_deg[r.w], 1);
    }
}

// exclusive scan of 8192 degrees; re-zero g_deg after reading (replay invariant)
__global__ void scan_kernel() {
    __shared__ int wsum[32];
    int t = threadIdx.x, lane = t & 31, wid = t >> 5;
    int base = t * 8;
    int l[8];
    int s = 0;
#pragma unroll
    for (int j = 0; j < 8; ++j) { s += g_deg[base + j]; l[j] = s; }
#pragma unroll
    for (int j = 0; j < 8; ++j) g_deg[base + j] = 0;
    int tot = s;
#pragma unroll
    for (int o = 1; o < 32; o <<= 1) {
        int v = __shfl_up_sync(0xffffffffu, s, o);
        if (lane >= o) s += v;
    }
    if (lane == 31) wsum[wid] = s;
    __syncthreads();
    if (wid == 0) {
        int w = wsum[lane];
#pragma unroll
        for (int o = 1; o < 32; o <<= 1) {
            int v = __shfl_up_sync(0xffffffffu, w, o);
            if (lane >= o) w += v;
        }
        wsum[lane] = w;
    }
    __syncthreads();
    int warp_base = wid ? wsum[wid - 1] : 0;
    int excl = warp_base + s - tot;
#pragma unroll
    for (int j = 0; j < 8; ++j) {
        int e = excl + ((j == 0) ? 0 : l[j - 1]);
        g_off[base + j] = e;
        g_cur[base + j] = e;
    }
    if (t == 1023) g_off[NN] = warp_base + s;
}

// 4 edges/thread, int4 loads of both adj rows
__global__ void scatter_kernel(const int* __restrict__ adj) {
    int e4 = blockIdx.x * 256 + threadIdx.x;   // 0..65535
    int4 r = reinterpret_cast<const int4*>(adj)[e4];
    int4 c = reinterpret_cast<const int4*>(adj)[NE / 4 + e4];
    g_col[atomicAdd(&g_cur[r.x], 1)] = c.x;
    g_col[atomicAdd(&g_cur[r.y], 1)] = c.y;
    g_col[atomicAdd(&g_cur[r.z], 1)] = c.z;
    g_col[atomicAdd(&g_cur[r.w], 1)] = c.w;
}

// one block per node: gather fp16 neighbor rows (4-edge unroll), f32 acc,
// write h^T contiguously: g_hT[r*DF + d]
__global__ void agg_kernel() {
    int r = blockIdx.x;
    int t = threadIdx.x;  // 0..127 -> 512 feats as 4 halves each
    int beg = g_off[r];
    int end = g_off[r + 1];
    const uint2* xh = reinterpret_cast<const uint2*>(g_xh);
    float ax = 0.f, ay = 0.f, az = 0.f, aw = 0.f;
    int j = beg;
    for (; j + 4 <= end; j += 4) {
        int c0 = g_col[j], c1 = g_col[j + 1], c2 = g_col[j + 2], c3 = g_col[j + 3];
        uint2 v0 = xh[(size_t)c0 * 128 + t];
        uint2 v1 = xh[(size_t)c1 * 128 + t];
        uint2 v2 = xh[(size_t)c2 * 128 + t];
        uint2 v3 = xh[(size_t)c3 * 128 + t];
#define ACCUM(v) do {                                              \
        __half2 h0 = *reinterpret_cast<__half2*>(&(v).x);          \
        __half2 h1 = *reinterpret_cast<__half2*>(&(v).y);          \
        float2 f0 = __half22float2(h0);                            \
        float2 f1 = __half22float2(h1);                            \
        ax += f0.x; ay += f0.y; az += f1.x; aw += f1.y; } while (0)
        ACCUM(v0); ACCUM(v1); ACCUM(v2); ACCUM(v3);
    }
    for (; j < end; ++j) {
        int c = g_col[j];
        uint2 v = xh[(size_t)c * 128 + t];
        ACCUM(v);
    }
#undef ACCUM
    float inv = 1.0f / fmaxf((float)(end - beg), 1.0f);
    __half2 o0 = __floats2half2_rn(ax * inv, ay * inv);
    __half2 o1 = __floats2half2_rn(az * inv, aw * inv);
    uint2 v;
    v.x = *reinterpret_cast<uint32_t*>(&o0);
    v.y = *reinterpret_cast<uint32_t*>(&o1);
    *reinterpret_cast<uint2*>(g_hT + (size_t)r * DF + t * 4) = v;
}

// ---------------- balanced persistent fp16 GEMM, fused relu ----------------
#define BM 128
#define BN 128
#define BK 64
#define NKC 128
#define TOTC 32768
#define TILE_BYTES 16384
#define A_REGION 0
#define B_REGION 32768
#define GEMM_SMEM 81920

__device__ __forceinline__ int cta_of(int c, int G) {
    return (int)(((long long)(c + 1) * G - 1) / TOTC);
}

__global__ __launch_bounds__(256, 1)
void gemm_kernel(const float* __restrict__ W, float* __restrict__ out, int G) {
    extern __shared__ char smem[];
    __shared__ int s_old;
    uint32_t sb = smem_u32(smem);
    int tid  = threadIdx.x;
    int wid  = tid >> 5;
    int lane = tid & 31;

    int warp_m = (wid & 1) * 64;
    int warp_n = (wid >> 1) * 32;
    int lq = lane & 3, lh = lane >> 2;

    int a_r_lane = (lane & 7) + 8 * ((lane >> 3) & 1);
    uint32_t a_kx = (uint32_t)(16 * (lane >> 4));
    uint32_t a_row128[4], a_xr[4];
#pragma unroll
    for (int mt = 0; mt < 4; ++mt) {
        int r = warp_m + mt * 16 + a_r_lane;
        a_row128[mt] = (uint32_t)(r * 128);
        a_xr[mt] = (uint32_t)((r & 7) << 4);
    }
    int g_grp = lane >> 3;
    int kr_local = (g_grp & 1) * 8 + (lane & 7);
    uint32_t b_off[2];
#pragma unroll
    for (int p = 0; p < 2; ++p) {
        int nc = warp_n + (2 * p + (g_grp >> 1)) * 8;
        b_off[p] = (uint32_t)(kr_local * 256 + ((nc * 2) ^ ((lane & 7) << 4)));
    }

    int a_r0 = tid >> 4;
    int a_c4 = tid & 15;
    int b_k  = tid >> 4;
    int b_nc = tid & 15;

    const __half* B = g_hT;
    float4 areg[8];

    int cta = blockIdx.x;
    int s = (int)(((long long)TOTC * cta) / G);
    int e = (int)(((long long)TOTC * (cta + 1)) / G);

    while (s < e) {
        int tile = s >> 7;
        int k0 = s - (tile << 7);
        int kend = e - (tile << 7);
        if (kend > NKC) kend = NKC;
        int nk = kend - k0;
        int m0 = (tile & 63) * BM;
        int n0 = (tile >> 6) * BN;
        bool full = (k0 == 0 && kend == NKC);

        float acc[4][4][4];
#pragma unroll
        for (int mt = 0; mt < 4; ++mt)
#pragma unroll
            for (int nt = 0; nt < 4; ++nt)
#pragma unroll
                for (int i = 0; i < 4; ++i) acc[mt][nt][i] = 0.f;

        auto ldA = [&](int kt) {
#pragma unroll
            for (int i = 0; i < 8; ++i) {
                int row = a_r0 + i * 16;
                areg[i] = *reinterpret_cast<const float4*>(
                    W + (size_t)(m0 + row) * NN + kt * BK + a_c4 * 4);
            }
        };
        auto stsA = [&](int stage) {
            char* ab = smem + A_REGION + stage * TILE_BYTES;
            int colb = a_c4 * 8;
#pragma unroll
            for (int i = 0; i < 8; ++i) {
                int row = a_r0 + i * 16;
                uint32_t off = (uint32_t)(row * 128 + (colb ^ ((row & 7) << 4)));
                __half2 h0 = __floats2half2_rn(areg[i].x, areg[i].y);
                __half2 h1 = __floats2half2_rn(areg[i].z, areg[i].w);
                uint2 v;
                v.x = *reinterpret_cast<uint32_t*>(&h0);
                v.y = *reinterpret_cast<uint32_t*>(&h1);
                *reinterpret_cast<uint2*>(ab + off) = v;
            }
        };
        auto cpB = [&](int kt, int stage) {
            uint32_t bbuf = sb + B_REGION + stage * TILE_BYTES;
#pragma unroll
            for (int i = 0; i < 4; ++i) {
                int k = b_k + i * 16;
                uint32_t so = (uint32_t)(k * 256 + ((b_nc * 16) ^ ((k & 7) << 4)));
                cp_async16(bbuf + so, B + (size_t)(kt * BK + k) * DF + n0 + b_nc * 8);
            }
            CP_COMMIT();
        };

        ldA(k0);
        cpB(k0, 0);
        if (nk > 1) cpB(k0 + 1, 1);
        stsA(0);
        if (nk > 1) ldA(k0 + 1);

        for (int i = 0; i < nk; ++i) {
            if (i == nk - 1) { CP_WAIT0(); } else { CP_WAIT1(); }
            __syncthreads();

            if (i + 1 < nk) stsA((i + 1) & 1);
            if (i + 2 < nk) {
                ldA(k0 + i + 2);
                cpB(k0 + i + 2, (i + 2) % 3);
            }

            uint32_t abuf = sb + A_REGION + (i & 1) * TILE_BYTES;
            uint32_t bbuf = sb + B_REGION + (i % 3) * TILE_BYTES;

#pragma unroll
            for (int c = 0; c < 4; ++c) {
                uint32_t cb = (uint32_t)(c * 32);
                uint32_t af[4][4];
#pragma unroll
                for (int mt = 0; mt < 4; ++mt) {
                    uint32_t ptr = abuf + a_row128[mt] + ((cb + a_kx) ^ a_xr[mt]);
                    LDSM4(af[mt][0], af[mt][1], af[mt][2], af[mt][3], ptr);
                }
                uint32_t bf[4][2];
#pragma unroll
                for (int p = 0; p < 2; ++p) {
                    uint32_t ptr = bbuf + (uint32_t)(c * 4096) + b_off[p];
                    uint32_t r0, r1, r2, r3;
                    LDSM4T(r0, r1, r2, r3, ptr);
                    bf[2 * p][0] = r0;     bf[2 * p][1] = r1;
                    bf[2 * p + 1][0] = r2; bf[2 * p + 1][1] = r3;
                }
#pragma unroll
                for (int mt = 0; mt < 4; ++mt)
#pragma unroll
                    for (int nt = 0; nt < 4; ++nt)
                        mma_f16(acc[mt][nt],
                                af[mt][0], af[mt][1], af[mt][2], af[mt][3],
                                bf[nt][0], bf[nt][1]);
            }
        }

#pragma unroll
        for (int mt = 0; mt < 4; ++mt) {
            int m_lo = m0 + warp_m + mt * 16 + lh;
            int m_hi = m_lo + 8;
#pragma unroll
            for (int nt = 0; nt < 4; ++nt) {
                int nb = n0 + warp_n + nt * 8 + 2 * lq;
                float* o0 = out + (size_t)nb * NN;
                float* o1 = o0 + NN;
                if (full) {
                    o0[m_lo] = fmaxf(acc[mt][nt][0], 0.f);
                    o1[m_lo] = fmaxf(acc[mt][nt][1], 0.f);
                    o0[m_hi] = fmaxf(acc[mt][nt][2], 0.f);
                    o1[m_hi] = fmaxf(acc[mt][nt][3], 0.f);
                } else {
                    atomicAdd(o0 + m_lo, acc[mt][nt][0]);
                    atomicAdd(o1 + m_lo, acc[mt][nt][1]);
                    atomicAdd(o0 + m_hi, acc[mt][nt][2]);
                    atomicAdd(o1 + m_hi, acc[mt][nt][3]);
                }
            }
        }

        if (!full) {
            int writers = cta_of(tile * NKC + NKC - 1, G) - cta_of(tile * NKC, G) + 1;
            __threadfence();
            __syncthreads();
            if (tid == 0) s_old = atomicAdd(&g_cnt[tile], 1);
            __syncthreads();
            if (s_old == writers - 1) {
                __threadfence();
#pragma unroll
                for (int i = 0; i < 16; ++i) {
                    int idx = tid + i * 256;
                    int row = idx >> 5, c4 = idx & 31;
                    float4* pp = reinterpret_cast<float4*>(
                        out + (size_t)(n0 + row) * NN + m0) + c4;
                    float4 v = *pp;
                    v.x = fmaxf(v.x, 0.f); v.y = fmaxf(v.y, 0.f);
                    v.z = fmaxf(v.z, 0.f); v.w = fmaxf(v.w, 0.f);
                    *pp = v;
                }
                if (tid == 0) g_cnt[tile] = 0;   // replay invariant
            }
        }
        __syncthreads();

        s = (tile << 7) + kend;
    }
}

// ---------------- launcher ----------------
extern "C" void kernel_launch(void* const* d_in, const int* in_sizes, int n_in,
                              void* d_out, int out_size) {
    (void)in_sizes; (void)n_in; (void)out_size;
    const float* x   = (const float*)d_in[0];   // [512, 8192] f32
    const int*   adj = (const int*)d_in[1];     // [2, 262144] i32
    const float* W   = (const float*)d_in[2];   // [8192, 8192] f32
    float* out = (float*)d_out;                 // [512, 8192] f32

    int dev = 0, G = 148;
    cudaGetDevice(&dev);
    cudaDeviceGetAttribute(&G, cudaDevAttrMultiProcessorCount, dev);

    k0_kernel<<<8448, 256>>>(x, out, adj);
    scan_kernel<<<1, 1024>>>();
    scatter_kernel<<<NE / 1024, 256>>>(adj);
    agg_kernel<<<NN, 128>>>();

    cudaFuncSetAttribute(gemm_kernel, cudaFuncAttributeMaxDynamicSharedMemorySize, GEMM_SMEM);
    gemm_kernel<<<G, 256, GEMM_SMEM>>>(W, out, G);
}

// round 13
// speedup vs baseline: 2.1178x; 1.0194x over previous
#include <cuda_runtime.h>
#include <cuda_fp16.h>
#include <cstdint>
#include <cstddef>

#define NN 8192      // nodes == in_feats
#define DF 512       // feature dim
#define NE 262144    // edges

// ---------------- device scratch (no allocations allowed) ----------------
// g_deg / g_cnt are zero at module load; every run re-zeroes them after use,
// so each graph replay deterministically sees zeroed state.
__device__ int    g_deg[NN];
__device__ int    g_off[NN + 1];
__device__ int    g_cur[NN];
__device__ int    g_col[NE];
__device__ int    g_cnt[256];                 // split-tile completion counters
__device__ __half g_xh[(size_t)NN * DF];      // [node, feat] fp16, 8MB
__device__ __half g_hT[(size_t)NN * DF];      // [node(k), feat(n)] fp16 B operand, 8MB

// ---------------- helpers ----------------
#define GRIDDEP_WAIT() asm volatile("griddepcontrol.wait;" ::: "memory")

__device__ __forceinline__ uint32_t smem_u32(const void* p) {
    uint32_t a;
    asm("{ .reg .u64 t; cvta.to.shared.u64 t, %1; cvt.u32.u64 %0, t; }"
        : "=r"(a) : "l"(p));
    return a;
}
__device__ __forceinline__ void cp_async16(uint32_t saddr, const void* gaddr) {
    asm volatile("cp.async.cg.shared.global [%0], [%1], 16;"
                 :: "r"(saddr), "l"(gaddr) : "memory");
}
#define CP_COMMIT() asm volatile("cp.async.commit_group;" ::: "memory")
#define CP_WAIT1()  asm volatile("cp.async.wait_group 1;"  ::: "memory")
#define CP_WAIT0()  asm volatile("cp.async.wait_group 0;"  ::: "memory")

#define LDSM4(r0, r1, r2, r3, addr) \
    asm volatile("ldmatrix.sync.aligned.m8n8.x4.shared.b16 {%0,%1,%2,%3}, [%4];" \
                 : "=r"(r0), "=r"(r1), "=r"(r2), "=r"(r3) : "r"(addr))
#define LDSM4T(r0, r1, r2, r3, addr) \
    asm volatile("ldmatrix.sync.aligned.m8n8.x4.trans.shared.b16 {%0,%1,%2,%3}, [%4];" \
                 : "=r"(r0), "=r"(r1), "=r"(r2), "=r"(r3) : "r"(addr))

__device__ __forceinline__ void mma_f16(float* c,
                                        uint32_t a0, uint32_t a1, uint32_t a2, uint32_t a3,
                                        uint32_t b0, uint32_t b1) {
    asm volatile(
        "mma.sync.aligned.m16n8k16.row.col.f32.f16.f16.f32 "
        "{%0,%1,%2,%3}, {%4,%5,%6,%7}, {%8,%9}, {%0,%1,%2,%3};"
        : "+f"(c[0]), "+f"(c[1]), "+f"(c[2]), "+f"(c[3])
        : "r"(a0), "r"(a1), "r"(a2), "r"(a3), "r"(b0), "r"(b1));
}

// ---------------- fused prep head ----------------
// blocks [0,256): degree count, 4 edges/thread (first -> atomic tail hides
// under the bandwidth blocks that follow)
// blocks [256,4352): transpose x [DF,NN] f32 -> g_xh [NN,DF] fp16
// blocks [4352,8448): zero out
__global__ void k0_kernel(const float* __restrict__ x, float* __restrict__ out,
                          const int* __restrict__ adj) {
    int b = blockIdx.x;
    int tid = threadIdx.x;
    if (b < 256) {
        int e4 = b * 256 + tid;                       // 0..65535, 4 edges each
        int4 r = reinterpret_cast<const int4*>(adj)[e4];
        atomicAdd(&g_deg[r.x], 1);
        atomicAdd(&g_deg[r.y], 1);
        atomicAdd(&g_deg[r.z], 1);
        atomicAdd(&g_deg[r.w], 1);
    } else if (b < 4352) {
        __shared__ float tile[32][33];
        int bb = b - 256;
        int n0 = (bb & 255) * 32;
        int d0 = (bb >> 8) * 32;
        int tx = tid & 31, ty = tid >> 5;
#pragma unroll
        for (int i = 0; i < 32; i += 8)
            tile[ty + i][tx] = x[(size_t)(d0 + ty + i) * NN + n0 + tx];
        __syncthreads();
#pragma unroll
        for (int i = 0; i < 32; i += 8)
            g_xh[(size_t)(n0 + ty + i) * DF + d0 + tx] = __float2half_rn(tile[tx][ty + i]);
    } else {
        size_t i = ((size_t)(b - 4352) * 256 + tid) * 4;
        *reinterpret_cast<float4*>(out + i) = make_float4(0.f, 0.f, 0.f, 0.f);
    }
}

// exclusive scan of 8192 degrees; re-zero g_deg after reading (replay invariant)
__global__ void scan_kernel() {
    GRIDDEP_WAIT();
    __shared__ int wsum[32];
    int t = threadIdx.x, lane = t & 31, wid = t >> 5;
    int base = t * 8;
    int l[8];
    int s = 0;
#pragma unroll
    for (int j = 0; j < 8; ++j) { s += g_deg[base + j]; l[j] = s; }
#pragma unroll
    for (int j = 0; j < 8; ++j) g_deg[base + j] = 0;
    int tot = s;
#pragma unroll
    for (int o = 1; o < 32; o <<= 1) {
        int v = __shfl_up_sync(0xffffffffu, s, o);
        if (lane >= o) s += v;
    }
    if (lane == 31) wsum[wid] = s;
    __syncthreads();
    if (wid == 0) {
        int w = wsum[lane];
#pragma unroll
        for (int o = 1; o < 32; o <<= 1) {
            int v = __shfl_up_sync(0xffffffffu, w, o);
            if (lane >= o) w += v;
        }
        wsum[lane] = w;
    }
    __syncthreads();
    int warp_base = wid ? wsum[wid - 1] : 0;
    int excl = warp_base + s - tot;
#pragma unroll
    for (int j = 0; j < 8; ++j) {
        int e = excl + ((j == 0) ? 0 : l[j - 1]);
        g_off[base + j] = e;
        g_cur[base + j] = e;
    }
    if (t == 1023) g_off[NN] = warp_base + s;
}

// 4 edges/thread, int4 loads of both adj rows
__global__ void scatter_kernel(const int* __restrict__ adj) {
    GRIDDEP_WAIT();
    int e4 = blockIdx.x * 256 + threadIdx.x;   // 0..65535
    int4 r = reinterpret_cast<const int4*>(adj)[e4];
    int4 c = reinterpret_cast<const int4*>(adj)[NE / 4 + e4];
    g_col[atomicAdd(&g_cur[r.x], 1)] = c.x;
    g_col[atomicAdd(&g_cur[r.y], 1)] = c.y;
    g_col[atomicAdd(&g_cur[r.z], 1)] = c.z;
    g_col[atomicAdd(&g_cur[r.w], 1)] = c.w;
}

// one block per node: gather fp16 neighbor rows (4-edge unroll), f32 acc,
// write h^T contiguously: g_hT[r*DF + d]
__global__ void agg_kernel() {
    GRIDDEP_WAIT();
    int r = blockIdx.x;
    int t = threadIdx.x;  // 0..127 -> 512 feats as 4 halves each
    int beg = g_off[r];
    int end = g_off[r + 1];
    const uint2* xh = reinterpret_cast<const uint2*>(g_xh);
    float ax = 0.f, ay = 0.f, az = 0.f, aw = 0.f;
    int j = beg;
    for (; j + 4 <= end; j += 4) {
        int c0 = g_col[j], c1 = g_col[j + 1], c2 = g_col[j + 2], c3 = g_col[j + 3];
        uint2 v0 = xh[(size_t)c0 * 128 + t];
        uint2 v1 = xh[(size_t)c1 * 128 + t];
        uint2 v2 = xh[(size_t)c2 * 128 + t];
        uint2 v3 = xh[(size_t)c3 * 128 + t];
#define ACCUM(v) do {                                              \
        __half2 h0 = *reinterpret_cast<__half2*>(&(v).x);          \
        __half2 h1 = *reinterpret_cast<__half2*>(&(v).y);          \
        float2 f0 = __half22float2(h0);                            \
        float2 f1 = __half22float2(h1);                            \
        ax += f0.x; ay += f0.y; az += f1.x; aw += f1.y; } while (0)
        ACCUM(v0); ACCUM(v1); ACCUM(v2); ACCUM(v3);
    }
    for (; j < end; ++j) {
        int c = g_col[j];
        uint2 v = xh[(size_t)c * 128 + t];
        ACCUM(v);
    }
#undef ACCUM
    float inv = 1.0f / fmaxf((float)(end - beg), 1.0f);
    __half2 o0 = __floats2half2_rn(ax * inv, ay * inv);
    __half2 o1 = __floats2half2_rn(az * inv, aw * inv);
    uint2 v;
    v.x = *reinterpret_cast<uint32_t*>(&o0);
    v.y = *reinterpret_cast<uint32_t*>(&o1);
    *reinterpret_cast<uint2*>(g_hT + (size_t)r * DF + t * 4) = v;
}

// ---------------- balanced persistent fp16 GEMM, fused relu ----------------
#define BM 128
#define BN 128
#define BK 64
#define NKC 128
#define TOTC 32768
#define TILE_BYTES 16384
#define A_REGION 0
#define B_REGION 32768
#define GEMM_SMEM 81920

__device__ __forceinline__ int cta_of(int c, int G) {
    return (int)(((long long)(c + 1) * G - 1) / TOTC);
}

__global__ __launch_bounds__(256, 1)
void gemm_kernel(const float* __restrict__ W, float* __restrict__ out, int G) {
    extern __shared__ char smem[];
    __shared__ int s_old;
    uint32_t sb = smem_u32(smem);
    int tid  = threadIdx.x;
    int wid  = tid >> 5;
    int lane = tid & 31;

    int warp_m = (wid & 1) * 64;
    int warp_n = (wid >> 1) * 32;
    int lq = lane & 3, lh = lane >> 2;

    int a_r_lane = (lane & 7) + 8 * ((lane >> 3) & 1);
    uint32_t a_kx = (uint32_t)(16 * (lane >> 4));
    uint32_t a_row128[4], a_xr[4];
#pragma unroll
    for (int mt = 0; mt < 4; ++mt) {
        int r = warp_m + mt * 16 + a_r_lane;
        a_row128[mt] = (uint32_t)(r * 128);
        a_xr[mt] = (uint32_t)((r & 7) << 4);
    }
    int g_grp = lane >> 3;
    int kr_local = (g_grp & 1) * 8 + (lane & 7);
    uint32_t b_off[2];
#pragma unroll
    for (int p = 0; p < 2; ++p) {
        int nc = warp_n + (2 * p + (g_grp >> 1)) * 8;
        b_off[p] = (uint32_t)(kr_local * 256 + ((nc * 2) ^ ((lane & 7) << 4)));
    }

    int a_r0 = tid >> 4;
    int a_c4 = tid & 15;
    int b_k  = tid >> 4;
    int b_nc = tid & 15;

    const __half* B = g_hT;
    float4 areg[8];
    bool first = true;

    int cta = blockIdx.x;
    int s = (int)(((long long)TOTC * cta) / G);
    int e = (int)(((long long)TOTC * (cta + 1)) / G);

    while (s < e) {
        int tile = s >> 7;
        int k0 = s - (tile << 7);
        int kend = e - (tile << 7);
        if (kend > NKC) kend = NKC;
        int nk = kend - k0;
        int m0 = (tile & 63) * BM;
        int n0 = (tile >> 6) * BN;
        bool full = (k0 == 0 && kend == NKC);

        float acc[4][4][4];
#pragma unroll
        for (int mt = 0; mt < 4; ++mt)
#pragma unroll
            for (int nt = 0; nt < 4; ++nt)
#pragma unroll
                for (int i = 0; i < 4; ++i) acc[mt][nt][i] = 0.f;

        auto ldA = [&](int kt) {
#pragma unroll
            for (int i = 0; i < 8; ++i) {
                int row = a_r0 + i * 16;
                areg[i] = *reinterpret_cast<const float4*>(
                    W + (size_t)(m0 + row) * NN + kt * BK + a_c4 * 4);
            }
        };
        auto stsA = [&](int stage) {
            char* ab = smem + A_REGION + stage * TILE_BYTES;
            int colb = a_c4 * 8;
#pragma unroll
            for (int i = 0; i < 8; ++i) {
                int row = a_r0 + i * 16;
                uint32_t off = (uint32_t)(row * 128 + (colb ^ ((row & 7) << 4)));
                __half2 h0 = __floats2half2_rn(areg[i].x, areg[i].y);
                __half2 h1 = __floats2half2_rn(areg[i].z, areg[i].w);
                uint2 v;
                v.x = *reinterpret_cast<uint32_t*>(&h0);
                v.y = *reinterpret_cast<uint32_t*>(&h1);
                *reinterpret_cast<uint2*>(ab + off) = v;
            }
        };
        auto cpB = [&](int kt, int stage) {
            uint32_t bbuf = sb + B_REGION + stage * TILE_BYTES;
#pragma unroll
            for (int i = 0; i < 4; ++i) {
                int k = b_k + i * 16;
                uint32_t so = (uint32_t)(k * 256 + ((b_nc * 16) ^ ((k & 7) << 4)));
                cp_async16(bbuf + so, B + (size_t)(kt * BK + k) * DF + n0 + b_nc * 8);
            }
            CP_COMMIT();
        };

        // First W chunk loads are input-only: issue them BEFORE the PDL wait
        // so agg's tail overlaps this CTA's A prefetch.
        ldA(k0);
        if (first) { GRIDDEP_WAIT(); first = false; }
        cpB(k0, 0);
        if (nk > 1) cpB(k0 + 1, 1);
        stsA(0);
        if (nk > 1) ldA(k0 + 1);

        for (int i = 0; i < nk; ++i) {
            if (i == nk - 1) { CP_WAIT0(); } else { CP_WAIT1(); }
            __syncthreads();

            if (i + 1 < nk) stsA((i + 1) & 1);
            if (i + 2 < nk) {
                ldA(k0 + i + 2);
                cpB(k0 + i + 2, (i + 2) % 3);
            }

            uint32_t abuf = sb + A_REGION + (i & 1) * TILE_BYTES;
            uint32_t bbuf = sb + B_REGION + (i % 3) * TILE_BYTES;

#pragma unroll
            for (int c = 0; c < 4; ++c) {
                uint32_t cb = (uint32_t)(c * 32);
                uint32_t af[4][4];
#pragma unroll
                for (int mt = 0; mt < 4; ++mt) {
                    uint32_t ptr = abuf + a_row128[mt] + ((cb + a_kx) ^ a_xr[mt]);
                    LDSM4(af[mt][0], af[mt][1], af[mt][2], af[mt][3], ptr);
                }
                uint32_t bf[4][2];
#pragma unroll
                for (int p = 0; p < 2; ++p) {
                    uint32_t ptr = bbuf + (uint32_t)(c * 4096) + b_off[p];
                    uint32_t r0, r1, r2, r3;
                    LDSM4T(r0, r1, r2, r3, ptr);
                    bf[2 * p][0] = r0;     bf[2 * p][1] = r1;
                    bf[2 * p + 1][0] = r2; bf[2 * p + 1][1] = r3;
                }
#pragma unroll
                for (int mt = 0; mt < 4; ++mt)
#pragma unroll
                    for (int nt = 0; nt < 4; ++nt)
                        mma_f16(acc[mt][nt],
                                af[mt][0], af[mt][1], af[mt][2], af[mt][3],
                                bf[nt][0], bf[nt][1]);
            }
        }

#pragma unroll
        for (int mt = 0; mt < 4; ++mt) {
            int m_lo = m0 + warp_m + mt * 16 + lh;
            int m_hi = m_lo + 8;
#pragma unroll
            for (int nt = 0; nt < 4; ++nt) {
                int nb = n0 + warp_n + nt * 8 + 2 * lq;
                float* o0 = out + (size_t)nb * NN;
                float* o1 = o0 + NN;
                if (full) {
                    o0[m_lo] = fmaxf(acc[mt][nt][0], 0.f);
                    o1[m_lo] = fmaxf(acc[mt][nt][1], 0.f);
                    o0[m_hi] = fmaxf(acc[mt][nt][2], 0.f);
                    o1[m_hi] = fmaxf(acc[mt][nt][3], 0.f);
                } else {
                    atomicAdd(o0 + m_lo, acc[mt][nt][0]);
                    atomicAdd(o1 + m_lo, acc[mt][nt][1]);
                    atomicAdd(o0 + m_hi, acc[mt][nt][2]);
                    atomicAdd(o1 + m_hi, acc[mt][nt][3]);
                }
            }
        }

        if (!full) {
            int writers = cta_of(tile * NKC + NKC - 1, G) - cta_of(tile * NKC, G) + 1;
            __threadfence();
            __syncthreads();
            if (tid == 0) s_old = atomicAdd(&g_cnt[tile], 1);
            __syncthreads();
            if (s_old == writers - 1) {
                __threadfence();
#pragma unroll
                for (int i = 0; i < 16; ++i) {
                    int idx = tid + i * 256;
                    int row = idx >> 5, c4 = idx & 31;
                    float4* pp = reinterpret_cast<float4*>(
                        out + (size_t)(n0 + row) * NN + m0) + c4;
                    float4 v = *pp;
                    v.x = fmaxf(v.x, 0.f); v.y = fmaxf(v.y, 0.f);
                    v.z = fmaxf(v.z, 0.f); v.w = fmaxf(v.w, 0.f);
                    *pp = v;
                }
                if (tid == 0) g_cnt[tile] = 0;   // replay invariant
            }
        }
        __syncthreads();

        s = (tile << 7) + kend;
    }
}

// ---------------- launcher ----------------
extern "C" void kernel_launch(void* const* d_in, const int* in_sizes, int n_in,
                              void* d_out, int out_size) {
    (void)in_sizes; (void)n_in; (void)out_size;
    const float* x   = (const float*)d_in[0];   // [512, 8192] f32
    const int*   adj = (const int*)d_in[1];     // [2, 262144] i32
    const float* W   = (const float*)d_in[2];   // [8192, 8192] f32
    float* out = (float*)d_out;                 // [512, 8192] f32

    int dev = 0, G = 148;
    cudaGetDevice(&dev);
    cudaDeviceGetAttribute(&G, cudaDevAttrMultiProcessorCount, dev);

    cudaFuncSetAttribute(gemm_kernel, cudaFuncAttributeMaxDynamicSharedMemorySize, GEMM_SMEM);

    // PDL attribute: dependent launches may begin while the predecessor
    // drains; each dependent kernel executes griddepcontrol.wait before
    // touching predecessor output.
    cudaLaunchAttribute attr[1];
    attr[0].id = cudaLaunchAttributeProgrammaticStreamSerialization;
    attr[0].val.programmaticStreamSerializationAllowed = 1;

    k0_kernel<<<8448, 256>>>(x, out, adj);

    {
        cudaLaunchConfig_t cfg = {};
        cfg.gridDim = dim3(1);  cfg.blockDim = dim3(1024);
        cfg.attrs = attr;       cfg.numAttrs = 1;
        cudaLaunchKernelEx(&cfg, scan_kernel);
    }
    {
        cudaLaunchConfig_t cfg = {};
        cfg.gridDim = dim3(NE / 1024);  cfg.blockDim = dim3(256);
        cfg.attrs = attr;               cfg.numAttrs = 1;
        cudaLaunchKernelEx(&cfg, scatter_kernel, adj);
    }
    {
        cudaLaunchConfig_t cfg = {};
        cfg.gridDim = dim3(NN);  cfg.blockDim = dim3(128);
        cfg.attrs = attr;        cfg.numAttrs = 1;
        cudaLaunchKernelEx(&cfg, agg_kernel);
    }
    {
        cudaLaunchConfig_t cfg = {};
        cfg.gridDim = dim3(G);   cfg.blockDim = dim3(256);
        cfg.dynamicSmemBytes = GEMM_SMEM;
        cfg.attrs = attr;        cfg.numAttrs = 1;
        cudaLaunchKernelEx(&cfg, gemm_kernel, W, out, G);
    }
}

// round 14
// speedup vs baseline: 2.1299x; 1.0057x over previous
#include <cuda_runtime.h>
#include <cuda_fp16.h>
#include <cstdint>
#include <cstddef>

#define NN 8192      // nodes == in_feats
#define DF 512       // feature dim
#define NE 262144    // edges

// ---------------- device scratch (no allocations allowed) ----------------
// g_deg / g_cnt are zero at module load; every run re-zeroes them after use,
// so each graph replay deterministically sees zeroed state.
__device__ int    g_deg[NN];
__device__ int    g_off[NN + 1];
__device__ int    g_cur[NN];
__device__ int    g_col[NE];
__device__ int    g_cnt[256];                 // split-tile completion counters
__device__ __half g_xh[(size_t)NN * DF];      // [node, feat] fp16, 8MB
__device__ __half g_hT[(size_t)NN * DF];      // [node(k), feat(n)] fp16 B operand, 8MB

// ---------------- helpers ----------------
#define GRIDDEP_WAIT() asm volatile("griddepcontrol.wait;" ::: "memory")

__device__ __forceinline__ uint32_t smem_u32(const void* p) {
    uint32_t a;
    asm("{ .reg .u64 t; cvta.to.shared.u64 t, %1; cvt.u32.u64 %0, t; }"
        : "=r"(a) : "l"(p));
    return a;
}
__device__ __forceinline__ void cp_async16(uint32_t saddr, const void* gaddr) {
    asm volatile("cp.async.cg.shared.global [%0], [%1], 16;"
                 :: "r"(saddr), "l"(gaddr) : "memory");
}
#define CP_COMMIT() asm volatile("cp.async.commit_group;" ::: "memory")
#define CP_WAIT1()  asm volatile("cp.async.wait_group 1;"  ::: "memory")
#define CP_WAIT0()  asm volatile("cp.async.wait_group 0;"  ::: "memory")

#define LDSM4(r0, r1, r2, r3, addr) \
    asm volatile("ldmatrix.sync.aligned.m8n8.x4.shared.b16 {%0,%1,%2,%3}, [%4];" \
                 : "=r"(r0), "=r"(r1), "=r"(r2), "=r"(r3) : "r"(addr))
#define LDSM4T(r0, r1, r2, r3, addr) \
    asm volatile("ldmatrix.sync.aligned.m8n8.x4.trans.shared.b16 {%0,%1,%2,%3}, [%4];" \
                 : "=r"(r0), "=r"(r1), "=r"(r2), "=r"(r3) : "r"(addr))

__device__ __forceinline__ void mma_f16(float* c,
                                        uint32_t a0, uint32_t a1, uint32_t a2, uint32_t a3,
                                        uint32_t b0, uint32_t b1) {
    asm volatile(
        "mma.sync.aligned.m16n8k16.row.col.f32.f16.f16.f32 "
        "{%0,%1,%2,%3}, {%4,%5,%6,%7}, {%8,%9}, {%0,%1,%2,%3};"
        : "+f"(c[0]), "+f"(c[1]), "+f"(c[2]), "+f"(c[3])
        : "r"(a0), "r"(a1), "r"(a2), "r"(a3), "r"(b0), "r"(b1));
}

// ---------------- fused prep head ----------------
// blocks [0,256): degree count, 4 edges/thread (first -> atomic tail hides
// under the bandwidth blocks that follow)
// blocks [256,4352): transpose x [DF,NN] f32 -> g_xh [NN,DF] fp16
// blocks [4352,8448): zero out
__global__ void k0_kernel(const float* __restrict__ x, float* __restrict__ out,
                          const int* __restrict__ adj) {
    int b = blockIdx.x;
    int tid = threadIdx.x;
    if (b < 256) {
        int e4 = b * 256 + tid;                       // 0..65535, 4 edges each
        int4 r = reinterpret_cast<const int4*>(adj)[e4];
        atomicAdd(&g_deg[r.x], 1);
        atomicAdd(&g_deg[r.y], 1);
        atomicAdd(&g_deg[r.z], 1);
        atomicAdd(&g_deg[r.w], 1);
    } else if (b < 4352) {
        __shared__ float tile[32][33];
        int bb = b - 256;
        int n0 = (bb & 255) * 32;
        int d0 = (bb >> 8) * 32;
        int tx = tid & 31, ty = tid >> 5;
#pragma unroll
        for (int i = 0; i < 32; i += 8)
            tile[ty + i][tx] = x[(size_t)(d0 + ty + i) * NN + n0 + tx];
        __syncthreads();
#pragma unroll
        for (int i = 0; i < 32; i += 8)
            g_xh[(size_t)(n0 + ty + i) * DF + d0 + tx] = __float2half_rn(tile[tx][ty + i]);
    } else {
        size_t i = ((size_t)(b - 4352) * 256 + tid) * 4;
        *reinterpret_cast<float4*>(out + i) = make_float4(0.f, 0.f, 0.f, 0.f);
    }
}

// exclusive scan of 8192 degrees; re-zero g_deg after reading (replay invariant)
__global__ void scan_kernel() {
    GRIDDEP_WAIT();
    __shared__ int wsum[32];
    int t = threadIdx.x, lane = t & 31, wid = t >> 5;
    int base = t * 8;
    int l[8];
    int s = 0;
#pragma unroll
    for (int j = 0; j < 8; ++j) { s += g_deg[base + j]; l[j] = s; }
#pragma unroll
    for (int j = 0; j < 8; ++j) g_deg[base + j] = 0;
    int tot = s;
#pragma unroll
    for (int o = 1; o < 32; o <<= 1) {
        int v = __shfl_up_sync(0xffffffffu, s, o);
        if (lane >= o) s += v;
    }
    if (lane == 31) wsum[wid] = s;
    __syncthreads();
    if (wid == 0) {
        int w = wsum[lane];
#pragma unroll
        for (int o = 1; o < 32; o <<= 1) {
            int v = __shfl_up_sync(0xffffffffu, w, o);
            if (lane >= o) w += v;
        }
        wsum[lane] = w;
    }
    __syncthreads();
    int warp_base = wid ? wsum[wid - 1] : 0;
    int excl = warp_base + s - tot;
#pragma unroll
    for (int j = 0; j < 8; ++j) {
        int e = excl + ((j == 0) ? 0 : l[j - 1]);
        g_off[base + j] = e;
        g_cur[base + j] = e;
    }
    if (t == 1023) g_off[NN] = warp_base + s;
}

// 4 edges/thread, int4 loads of both adj rows
__global__ void scatter_kernel(const int* __restrict__ adj) {
    GRIDDEP_WAIT();
    int e4 = blockIdx.x * 256 + threadIdx.x;   // 0..65535
    int4 r = reinterpret_cast<const int4*>(adj)[e4];
    int4 c = reinterpret_cast<const int4*>(adj)[NE / 4 + e4];
    g_col[atomicAdd(&g_cur[r.x], 1)] = c.x;
    g_col[atomicAdd(&g_cur[r.y], 1)] = c.y;
    g_col[atomicAdd(&g_cur[r.z], 1)] = c.z;
    g_col[atomicAdd(&g_cur[r.w], 1)] = c.w;
}

// one block per node: gather fp16 neighbor rows (4-edge unroll), f32 acc,
// write h^T contiguously: g_hT[r*DF + d]
__global__ void agg_kernel() {
    GRIDDEP_WAIT();
    int r = blockIdx.x;
    int t = threadIdx.x;  // 0..127 -> 512 feats as 4 halves each
    int beg = g_off[r];
    int end = g_off[r + 1];
    const uint2* xh = reinterpret_cast<const uint2*>(g_xh);
    float ax = 0.f, ay = 0.f, az = 0.f, aw = 0.f;
    int j = beg;
    for (; j + 4 <= end; j += 4) {
        int c0 = g_col[j], c1 = g_col[j + 1], c2 = g_col[j + 2], c3 = g_col[j + 3];
        uint2 v0 = xh[(size_t)c0 * 128 + t];
        uint2 v1 = xh[(size_t)c1 * 128 + t];
        uint2 v2 = xh[(size_t)c2 * 128 + t];
        uint2 v3 = xh[(size_t)c3 * 128 + t];
#define ACCUM(v) do {                                              \
        __half2 h0 = *reinterpret_cast<__half2*>(&(v).x);          \
        __half2 h1 = *reinterpret_cast<__half2*>(&(v).y);          \
        float2 f0 = __half22float2(h0);                            \
        float2 f1 = __half22float2(h1);                            \
        ax += f0.x; ay += f0.y; az += f1.x; aw += f1.y; } while (0)
        ACCUM(v0); ACCUM(v1); ACCUM(v2); ACCUM(v3);
    }
    for (; j < end; ++j) {
        int c = g_col[j];
        uint2 v = xh[(size_t)c * 128 + t];
        ACCUM(v);
    }
#undef ACCUM
    float inv = 1.0f / fmaxf((float)(end - beg), 1.0f);
    __half2 o0 = __floats2half2_rn(ax * inv, ay * inv);
    __half2 o1 = __floats2half2_rn(az * inv, aw * inv);
    uint2 v;
    v.x = *reinterpret_cast<uint32_t*>(&o0);
    v.y = *reinterpret_cast<uint32_t*>(&o1);
    *reinterpret_cast<uint2*>(g_hT + (size_t)r * DF + t * 4) = v;
}

// ---------------- balanced persistent fp16 GEMM, fused relu ----------------
#define BM 128
#define BN 128
#define BK 64
#define NKC 128
#define TOTC 32768
#define TILE_BYTES 16384
#define A_REGION 0
#define B_REGION 32768
#define GEMM_SMEM 81920

__device__ __forceinline__ int cta_of(int c, int G) {
    return (int)(((long long)(c + 1) * G - 1) / TOTC);
}

__global__ __launch_bounds__(256, 1)
void gemm_kernel(const float* __restrict__ W, float* __restrict__ out, int G) {
    extern __shared__ char smem[];
    __shared__ int s_old;
    uint32_t sb = smem_u32(smem);
    int tid  = threadIdx.x;
    int wid  = tid >> 5;
    int lane = tid & 31;

    int warp_m = (wid & 1) * 64;
    int warp_n = (wid >> 1) * 32;
    int lq = lane & 3, lh = lane >> 2;

    int a_r_lane = (lane & 7) + 8 * ((lane >> 3) & 1);
    uint32_t a_kx = (uint32_t)(16 * (lane >> 4));
    uint32_t a_row128[4], a_xr[4];
#pragma unroll
    for (int mt = 0; mt < 4; ++mt) {
        int r = warp_m + mt * 16 + a_r_lane;
        a_row128[mt] = (uint32_t)(r * 128);
        a_xr[mt] = (uint32_t)((r & 7) << 4);
    }
    int g_grp = lane >> 3;
    int kr_local = (g_grp & 1) * 8 + (lane & 7);
    uint32_t b_off[2];
#pragma unroll
    for (int p = 0; p < 2; ++p) {
        int nc = warp_n + (2 * p + (g_grp >> 1)) * 8;
        b_off[p] = (uint32_t)(kr_local * 256 + ((nc * 2) ^ ((lane & 7) << 4)));
    }

    int a_r0 = tid >> 4;
    int a_c4 = tid & 15;
    int b_k  = tid >> 4;
    int b_nc = tid & 15;

    const __half* B = g_hT;
    float4 areg[8];
    bool first = true;

    int cta = blockIdx.x;
    int s = (int)(((long long)TOTC * cta) / G);
    int e = (int)(((long long)TOTC * (cta + 1)) / G);

    while (s < e) {
        int tile = s >> 7;
        int k0 = s - (tile << 7);
        int kend = e - (tile << 7);
        if (kend > NKC) kend = NKC;
        int nk = kend - k0;
        int m0 = (tile & 63) * BM;
        int n0 = (tile >> 6) * BN;
        bool full = (k0 == 0 && kend == NKC);

        float acc[4][4][4];
#pragma unroll
        for (int mt = 0; mt < 4; ++mt)
#pragma unroll
            for (int nt = 0; nt < 4; ++nt)
#pragma unroll
                for (int i = 0; i < 4; ++i) acc[mt][nt][i] = 0.f;

        auto ldA = [&](int kt) {
#pragma unroll
            for (int i = 0; i < 8; ++i) {
                int row = a_r0 + i * 16;
                areg[i] = *reinterpret_cast<const float4*>(
                    W + (size_t)(m0 + row) * NN + kt * BK + a_c4 * 4);
            }
        };
        auto stsA = [&](int stage) {
            char* ab = smem + A_REGION + stage * TILE_BYTES;
            int colb = a_c4 * 8;
#pragma unroll
            for (int i = 0; i < 8; ++i) {
                int row = a_r0 + i * 16;
                uint32_t off = (uint32_t)(row * 128 + (colb ^ ((row & 7) << 4)));
                __half2 h0 = __floats2half2_rn(areg[i].x, areg[i].y);
                __half2 h1 = __floats2half2_rn(areg[i].z, areg[i].w);
                uint2 v;
                v.x = *reinterpret_cast<uint32_t*>(&h0);
                v.y = *reinterpret_cast<uint32_t*>(&h1);
                *reinterpret_cast<uint2*>(ab + off) = v;
            }
        };
        auto cpB = [&](int kt, int stage) {
            uint32_t bbuf = sb + B_REGION + stage * TILE_BYTES;
#pragma unroll
            for (int i = 0; i < 4; ++i) {
                int k = b_k + i * 16;
                uint32_t so = (uint32_t)(k * 256 + ((b_nc * 16) ^ ((k & 7) << 4)));
                cp_async16(bbuf + so, B + (size_t)(kt * BK + k) * DF + n0 + b_nc * 8);
            }
            CP_COMMIT();
        };

        // First W chunk loads are input-only: issue them BEFORE the PDL wait
        // so agg's tail overlaps this CTA's A prefetch.
        ldA(k0);
        if (first) { GRIDDEP_WAIT(); first = false; }
        cpB(k0, 0);
        if (nk > 1) cpB(k0 + 1, 1);
        stsA(0);
        if (nk > 1) ldA(k0 + 1);

        for (int i = 0; i < nk; ++i) {
            if (i == nk - 1) { CP_WAIT0(); } else { CP_WAIT1(); }
            __syncthreads();

            if (i + 1 < nk) stsA((i + 1) & 1);
            if (i + 2 < nk) {
                ldA(k0 + i + 2);
                cpB(k0 + i + 2, (i + 2) % 3);
            }

            uint32_t abuf = sb + A_REGION + (i & 1) * TILE_BYTES;
            uint32_t bbuf = sb + B_REGION + (i % 3) * TILE_BYTES;

#pragma unroll
            for (int c = 0; c < 4; ++c) {
                uint32_t cb = (uint32_t)(c * 32);
                uint32_t af[4][4];
#pragma unroll
                for (int mt = 0; mt < 4; ++mt) {
                    uint32_t ptr = abuf + a_row128[mt] + ((cb + a_kx) ^ a_xr[mt]);
                    LDSM4(af[mt][0], af[mt][1], af[mt][2], af[mt][3], ptr);
                }
                uint32_t bf[4][2];
#pragma unroll
                for (int p = 0; p < 2; ++p) {
                    uint32_t ptr = bbuf + (uint32_t)(c * 4096) + b_off[p];
                    uint32_t r0, r1, r2, r3;
                    LDSM4T(r0, r1, r2, r3, ptr);
                    bf[2 * p][0] = r0;     bf[2 * p][1] = r1;
                    bf[2 * p + 1][0] = r2; bf[2 * p + 1][1] = r3;
                }
#pragma unroll
                for (int mt = 0; mt < 4; ++mt)
#pragma unroll
                    for (int nt = 0; nt < 4; ++nt)
                        mma_f16(acc[mt][nt],
                                af[mt][0], af[mt][1], af[mt][2], af[mt][3],
                                bf[nt][0], bf[nt][1]);
            }
        }

#pragma unroll
        for (int mt = 0; mt < 4; ++mt) {
            int m_lo = m0 + warp_m + mt * 16 + lh;
            int m_hi = m_lo + 8;
#pragma unroll
            for (int nt = 0; nt < 4; ++nt) {
                int nb = n0 + warp_n + nt * 8 + 2 * lq;
                float* o0 = out + (size_t)nb * NN;
                float* o1 = o0 + NN;
                if (full) {
                    o0[m_lo] = fmaxf(acc[mt][nt][0], 0.f);
                    o1[m_lo] = fmaxf(acc[mt][nt][1], 0.f);
                    o0[m_hi] = fmaxf(acc[mt][nt][2], 0.f);
                    o1[m_hi] = fmaxf(acc[mt][nt][3], 0.f);
                } else {
                    atomicAdd(o0 + m_lo, acc[mt][nt][0]);
                    atomicAdd(o1 + m_lo, acc[mt][nt][1]);
                    atomicAdd(o0 + m_hi, acc[mt][nt][2]);
                    atomicAdd(o1 + m_hi, acc[mt][nt][3]);
                }
            }
        }

        if (!full) {
            int writers = cta_of(tile * NKC + NKC - 1, G) - cta_of(tile * NKC, G) + 1;
            __threadfence();
            __syncthreads();
            if (tid == 0) s_old = atomicAdd(&g_cnt[tile], 1);
            __syncthreads();
            if (s_old == writers - 1) {
                __threadfence();
#pragma unroll
                for (int i = 0; i < 16; ++i) {
                    int idx = tid + i * 256;
                    int row = idx >> 5, c4 = idx & 31;
                    float4* pp = reinterpret_cast<float4*>(
                        out + (size_t)(n0 + row) * NN + m0) + c4;
                    float4 v = *pp;
                    v.x = fmaxf(v.x, 0.f); v.y = fmaxf(v.y, 0.f);
                    v.z = fmaxf(v.z, 0.f); v.w = fmaxf(v.w, 0.f);
                    *pp = v;
                }
                if (tid == 0) g_cnt[tile] = 0;   // replay invariant
            }
        }
        __syncthreads();

        s = (tile << 7) + kend;
    }
}

// ---------------- launcher ----------------
extern "C" void kernel_launch(void* const* d_in, const int* in_sizes, int n_in,
                              void* d_out, int out_size) {
    (void)in_sizes; (void)n_in; (void)out_size;
    const float* x   = (const float*)d_in[0];   // [512, 8192] f32
    const int*   adj = (const int*)d_in[1];     // [2, 262144] i32
    const float* W   = (const float*)d_in[2];   // [8192, 8192] f32
    float* out = (float*)d_out;                 // [512, 8192] f32

    int dev = 0, G = 148;
    cudaGetDevice(&dev);
    cudaDeviceGetAttribute(&G, cudaDevAttrMultiProcessorCount, dev);

    cudaFuncSetAttribute(gemm_kernel, cudaFuncAttributeMaxDynamicSharedMemorySize, GEMM_SMEM);

    // PDL attribute: dependent launches may begin while the predecessor
    // drains; each dependent kernel executes griddepcontrol.wait before
    // touching predecessor output.
    cudaLaunchAttribute attr[1];
    attr[0].id = cudaLaunchAttributeProgrammaticStreamSerialization;
    attr[0].val.programmaticStreamSerializationAllowed = 1;

    k0_kernel<<<8448, 256>>>(x, out, adj);

    {
        cudaLaunchConfig_t cfg = {};
        cfg.gridDim = dim3(1);  cfg.blockDim = dim3(1024);
        cfg.attrs = attr;       cfg.numAttrs = 1;
        cudaLaunchKernelEx(&cfg, scan_kernel);
    }
    {
        cudaLaunchConfig_t cfg = {};
        cfg.gridDim = dim3(NE / 1024);  cfg.blockDim = dim3(256);
        cfg.attrs = attr;               cfg.numAttrs = 1;
        cudaLaunchKernelEx(&cfg, scatter_kernel, adj);
    }
    {
        cudaLaunchConfig_t cfg = {};
        cfg.gridDim = dim3(NN);  cfg.blockDim = dim3(128);
        cfg.attrs = attr;        cfg.numAttrs = 1;
        cudaLaunchKernelEx(&cfg, agg_kernel);
    }
    {
        cudaLaunchConfig_t cfg = {};
        cfg.gridDim = dim3(G);   cfg.blockDim = dim3(256);
        cfg.dynamicSmemBytes = GEMM_SMEM;
        cfg.attrs = attr;        cfg.numAttrs = 1;
        cudaLaunchKernelEx(&cfg, gemm_kernel, W, out, G);
    }
}